// round 3
// baseline (speedup 1.0000x reference)
#include <cuda_runtime.h>
#include <cuda_fp16.h>
#include <cstdint>

// Problem: B=128, L_IM=50, L_S=40, D=1024
// im = im_set[:,1:,:]  -> 49 valid rows, padded to 64 (masked rows zeroed)
// s  = s_seq[:,1:-2,:] -> 37 valid rows, padded to 40 (masked rows zeroed)
#define NBATCH 128
#define DDIM   1024
#define AROWS  64     // padded im rows per batch
#define SROWS  40     // padded s rows per batch

__device__ __align__(1024) __half g_A[(size_t)NBATCH * AROWS * DDIM];  // 16 MB
__device__ __align__(1024) __half g_S[(size_t)NBATCH * SROWS * DDIM];  // 10 MB

// ---------------- helpers ----------------
__device__ __forceinline__ uint32_t smem_u32(const void* p) {
    uint32_t a;
    asm("{ .reg .u64 t; cvta.to.shared.u64 t, %1; cvt.u32.u64 %0, t; }" : "=r"(a) : "l"(p));
    return a;
}

#define CP_ASYNC16(dst, src) \
    asm volatile("cp.async.cg.shared.global [%0], [%1], 16;" :: "r"(dst), "l"(src))
#define CP_COMMIT() asm volatile("cp.async.commit_group;" ::: "memory")
#define CP_WAIT2()  asm volatile("cp.async.wait_group 2;" ::: "memory")

#define LDSM4(r, addr) \
    asm volatile("ldmatrix.sync.aligned.m8n8.x4.shared.b16 {%0,%1,%2,%3}, [%4];" \
                 : "=r"((r)[0]), "=r"((r)[1]), "=r"((r)[2]), "=r"((r)[3]) : "r"(addr))

#define MMA16816(c, a, b0, b1) \
    asm volatile("mma.sync.aligned.m16n8k16.row.col.f32.f16.f16.f32 " \
                 "{%0,%1,%2,%3},{%4,%5,%6,%7},{%8,%9},{%0,%1,%2,%3};" \
                 : "+f"((c)[0]), "+f"((c)[1]), "+f"((c)[2]), "+f"((c)[3]) \
                 : "r"((a)[0]), "r"((a)[1]), "r"((a)[2]), "r"((a)[3]), "r"(b0), "r"(b1))

__device__ __forceinline__ float wsum(float v) {
#pragma unroll
    for (int m = 16; m > 0; m >>= 1) v += __shfl_xor_sync(0xffffffffu, v, m);
    return v;
}

// ------------- conversion kernels: fp32 -> fp16, mask-zeroed, padded -------------
// Each thread converts 8 floats.
__global__ void convA_kernel(const float* __restrict__ im, const int* __restrict__ im_len) {
    int u = blockIdx.x * blockDim.x + threadIdx.x;        // < 128*64*128 = 1048576
    int i  = u >> 13;
    int r  = (u >> 7) & 63;
    int d0 = (u & 127) << 3;
    int L = im_len[i] - 1;                                // valid rows (<=49)
    union { uint4 v; __half2 h[4]; } pk;
    if (r < L && r < 49) {
        const float* src = im + ((size_t)i * 50 + r + 1) * DDIM + d0;
        float4 f0 = ((const float4*)src)[0];
        float4 f1 = ((const float4*)src)[1];
        pk.h[0] = __float22half2_rn(make_float2(f0.x, f0.y));
        pk.h[1] = __float22half2_rn(make_float2(f0.z, f0.w));
        pk.h[2] = __float22half2_rn(make_float2(f1.x, f1.y));
        pk.h[3] = __float22half2_rn(make_float2(f1.z, f1.w));
    } else {
        pk.v = make_uint4(0, 0, 0, 0);
    }
    *((uint4*)(g_A + ((size_t)i * AROWS + r) * DDIM + d0)) = pk.v;
}

__global__ void convS_kernel(const float* __restrict__ s, const int* __restrict__ s_len) {
    int u = blockIdx.x * blockDim.x + threadIdx.x;        // < 128*40*128 = 655360
    int i   = u / (SROWS * 128);
    int rem = u - i * (SROWS * 128);
    int r  = rem >> 7;
    int d0 = (rem & 127) << 3;
    int L = s_len[i] - 3;                                 // valid rows (<=37)
    union { uint4 v; __half2 h[4]; } pk;
    if (r < L && r < 37) {
        const float* src = s + ((size_t)i * 40 + r + 1) * DDIM + d0;
        float4 f0 = ((const float4*)src)[0];
        float4 f1 = ((const float4*)src)[1];
        pk.h[0] = __float22half2_rn(make_float2(f0.x, f0.y));
        pk.h[1] = __float22half2_rn(make_float2(f0.z, f0.w));
        pk.h[2] = __float22half2_rn(make_float2(f1.x, f1.y));
        pk.h[3] = __float22half2_rn(make_float2(f1.z, f1.w));
    } else {
        pk.v = make_uint4(0, 0, 0, 0);
    }
    *((uint4*)(g_S + ((size_t)i * SROWS + r) * DDIM + d0)) = pk.v;
}

// ------------- GEMM + fused masked max/sum epilogue -------------
// CTA: 256 threads, tile M=128 (2 i), N=160 (4 j x 40), K=1024 in 16 chunks of 64 halves.
// Warp grid 4(m) x 2(n): warp tile 32 x 80.
// SMEM stage: A 128 rows x 144B + B 160 rows x 144B = 41472 B; 4 stages = 165888 B.
// Row pitch 144B (9 x 16B chunks) -> ldmatrix conflict-free, no swizzle needed.
#define PITCH     144
#define ASTAGE    18432              // 128*144
#define STAGE_SZ  41472              // ASTAGE + 160*144
#define NSTAGES   4
#define SMEM_BYTES (STAGE_SZ * NSTAGES)
#define CPITCH    168                // C smem pitch in floats

__device__ __forceinline__ void load_stage(uint32_t sbase, int stg, int kt,
                                           int ib, int jb, int tid) {
    uint32_t sa = sbase + stg * STAGE_SZ;
    const __half* gA = g_A + ((size_t)ib * 128) * DDIM + kt * 64;
    const __half* gB = g_S + ((size_t)jb * 160) * DDIM + kt * 64;
#pragma unroll
    for (int q = 0; q < 4; q++) {                         // A: 1024 16B chunks
        int idx = tid * 4 + q;
        int row = idx >> 3, c = idx & 7;
        CP_ASYNC16(sa + row * PITCH + c * 16,
                   (const char*)(gA + (size_t)row * DDIM) + c * 16);
    }
#pragma unroll
    for (int q = 0; q < 5; q++) {                         // B: 1280 16B chunks
        int idx = tid * 5 + q;
        int row = idx >> 3, c = idx & 7;
        CP_ASYNC16(sa + ASTAGE + row * PITCH + c * 16,
                   (const char*)(gB + (size_t)row * DDIM) + c * 16);
    }
}

__global__ void __launch_bounds__(256, 1) align_gemm_kernel(float* __restrict__ out) {
    extern __shared__ __align__(16) char smem[];
    const int tid  = threadIdx.x;
    const int lane = tid & 31;
    const int wid  = tid >> 5;
    const int wm   = wid & 3;        // 0..3 -> M offset wm*32
    const int wn   = wid >> 2;       // 0..1 -> N offset wn*80
    const int jb = blockIdx.x;       // 0..31
    const int ib = blockIdx.y;       // 0..63
    const uint32_t sbase = smem_u32(smem);

    // ldmatrix lane offsets
    const int quad = lane >> 3, r8 = lane & 7;
    const uint32_t a_lane = (uint32_t)((wm * 32 + (quad & 1) * 8 + r8) * PITCH + (quad >> 1) * 16);
    uint32_t b_lane[5];
#pragma unroll
    for (int nn = 0; nn < 5; nn++)
        b_lane[nn] = (uint32_t)(ASTAGE + (wn * 80 + nn * 16 + (quad >> 1) * 8 + r8) * PITCH
                                + (quad & 1) * 16);

    float c[2][10][4];
#pragma unroll
    for (int mt = 0; mt < 2; mt++)
#pragma unroll
        for (int nt = 0; nt < 10; nt++)
#pragma unroll
            for (int q = 0; q < 4; q++) c[mt][nt][q] = 0.0f;

    load_stage(sbase, 0, 0, ib, jb, tid); CP_COMMIT();
    load_stage(sbase, 1, 1, ib, jb, tid); CP_COMMIT();
    load_stage(sbase, 2, 2, ib, jb, tid); CP_COMMIT();

#pragma unroll 1
    for (int kt = 0; kt < 16; kt++) {
        CP_WAIT2();
        __syncthreads();
        if (kt + 3 < 16) load_stage(sbase, (kt + 3) & 3, kt + 3, ib, jb, tid);
        CP_COMMIT();

        const uint32_t stga = sbase + (kt & 3) * STAGE_SZ;
#pragma unroll
        for (int step = 0; step < 4; step++) {
            uint32_t areg[2][4], breg[5][4];
#pragma unroll
            for (int mt = 0; mt < 2; mt++)
                LDSM4(areg[mt], stga + a_lane + mt * 16 * PITCH + step * 32);
#pragma unroll
            for (int nn = 0; nn < 5; nn++)
                LDSM4(breg[nn], stga + b_lane[nn] + step * 32);
#pragma unroll
            for (int mt = 0; mt < 2; mt++)
#pragma unroll
                for (int nt = 0; nt < 10; nt++)
                    MMA16816(c[mt][nt], areg[mt], breg[nt >> 1][(nt & 1) * 2],
                             breg[nt >> 1][(nt & 1) * 2 + 1]);
        }
    }
    __syncthreads();   // all compute done; smem now reused for C

    // ---- store C tile to smem: [128][CPITCH] floats ----
    float* C = (float*)smem;
    float* acc = (float*)(smem + 128 * CPITCH * 4);          // 8 floats
    float* red = acc + 8;                                    // 320 floats
    if (tid < 8) acc[tid] = 0.0f;
#pragma unroll
    for (int mt = 0; mt < 2; mt++)
#pragma unroll
        for (int nt = 0; nt < 10; nt++) {
            int row = wm * 32 + mt * 16 + (lane >> 2);
            int col = wn * 80 + nt * 8 + (lane & 3) * 2;
            *(float2*)&C[row * CPITCH + col]       = make_float2(c[mt][nt][0], c[mt][nt][1]);
            *(float2*)&C[(row + 8) * CPITCH + col] = make_float2(c[mt][nt][2], c[mt][nt][3]);
        }
    __syncthreads();

    // ---- row part: for each row r (<49), max over w<37 per j-block; sum over r ----
    if (tid < 128) {
        int il = tid >> 6, ro = tid & 63;
        const float* Cr = &C[tid * CPITCH];
#pragma unroll
        for (int jj = 0; jj < 4; jj++) {
            float rm = Cr[jj * 40];
#pragma unroll
            for (int w = 1; w < 37; w++) rm = fmaxf(rm, Cr[jj * 40 + w]);
            float rs = wsum((ro < 49) ? rm : 0.0f);
            if (lane == 0) atomicAdd(&acc[il * 4 + jj], rs);
        }
    }
    // ---- col part: for each col w (<37), max over r<49; sum over w ----
    if (tid < 160) {
        int jj = tid / 40, w = tid - jj * 40;
#pragma unroll
        for (int il = 0; il < 2; il++) {
            const float* Cc = &C[il * 64 * CPITCH + tid];
            float cm = Cc[0];
#pragma unroll
            for (int r = 1; r < 49; r++) cm = fmaxf(cm, Cc[r * CPITCH]);
            red[il * 160 + tid] = (w < 37) ? cm : 0.0f;
        }
    }
    __syncthreads();
    if (tid < 8) {
        int il = tid >> 2, jj = tid & 3;
        float sum = acc[tid];
        const float* rp = &red[il * 160 + jj * 40];
#pragma unroll
        for (int w = 0; w < 37; w++) sum += rp[w];
        int ig = ib * 2 + il;
        int jg = jb * 4 + jj;
        out[ig * NBATCH + jg] = sum;
    }
}

extern "C" void kernel_launch(void* const* d_in, const int* in_sizes, int n_in,
                              void* d_out, int out_size) {
    (void)in_sizes; (void)n_in; (void)out_size;
    const float* im   = (const float*)d_in[0];
    const float* s    = (const float*)d_in[1];
    const int* im_len = (const int*)d_in[2];
    const int* s_len  = (const int*)d_in[3];
    float* out = (float*)d_out;

    convA_kernel<<<4096, 256>>>(im, im_len);
    convS_kernel<<<2560, 256>>>(s, s_len);

    cudaFuncSetAttribute(align_gemm_kernel,
                         cudaFuncAttributeMaxDynamicSharedMemorySize, SMEM_BYTES);
    dim3 grid(32, 64);
    align_gemm_kernel<<<grid, 256, SMEM_BYTES>>>(out);
}

// round 6
// speedup vs baseline: 1.6718x; 1.6718x over previous
#include <cuda_runtime.h>
#include <cuda_fp16.h>
#include <cstdint>

// Problem: B=128, L_IM=50, L_S=40, D=1024
// im = im_set[:,1:,:]  -> 49 valid rows, padded to 64 (masked rows zeroed)
// s  = s_seq[:,1:-2,:] -> 37 valid rows, padded to 40 (masked rows zeroed)
#define NBATCH 128
#define DDIM   1024
#define AROWS  64
#define SROWS  40

__device__ __align__(1024) __half g_A[(size_t)NBATCH * AROWS * DDIM];  // 16 MB
__device__ __align__(1024) __half g_S[(size_t)NBATCH * SROWS * DDIM];  // 10 MB

// ---------------- helpers ----------------
__device__ __forceinline__ uint32_t smem_u32(const void* p) {
    uint32_t a;
    asm("{ .reg .u64 t; cvta.to.shared.u64 t, %1; cvt.u32.u64 %0, t; }" : "=r"(a) : "l"(p));
    return a;
}

#define CP_ASYNC16(dst, src) \
    asm volatile("cp.async.cg.shared.global [%0], [%1], 16;" :: "r"(dst), "l"(src))
#define CP_COMMIT() asm volatile("cp.async.commit_group;" ::: "memory")
#define CP_WAIT2()  asm volatile("cp.async.wait_group 2;" ::: "memory")

#define LDSM4(r, addr) \
    asm volatile("ldmatrix.sync.aligned.m8n8.x4.shared.b16 {%0,%1,%2,%3}, [%4];" \
                 : "=r"((r)[0]), "=r"((r)[1]), "=r"((r)[2]), "=r"((r)[3]) : "r"(addr))

#define MMA16816(c, a, b0, b1) \
    asm volatile("mma.sync.aligned.m16n8k16.row.col.f32.f16.f16.f32 " \
                 "{%0,%1,%2,%3},{%4,%5,%6,%7},{%8,%9},{%0,%1,%2,%3};" \
                 : "+f"((c)[0]), "+f"((c)[1]), "+f"((c)[2]), "+f"((c)[3]) \
                 : "r"((a)[0]), "r"((a)[1]), "r"((a)[2]), "r"((a)[3]), "r"(b0), "r"(b1))

__device__ __forceinline__ float wsum(float v) {
#pragma unroll
    for (int m = 16; m > 0; m >>= 1) v += __shfl_xor_sync(0xffffffffu, v, m);
    return v;
}

// ------------- conversion kernels: fp32 -> fp16, mask-zeroed, padded -------------
__global__ void convA_kernel(const float* __restrict__ im, const int* __restrict__ im_len) {
    int u = blockIdx.x * blockDim.x + threadIdx.x;        // < 128*64*128
    int i  = u >> 13;
    int r  = (u >> 7) & 63;
    int d0 = (u & 127) << 3;
    int L = im_len[i] - 1;
    union { uint4 v; __half2 h[4]; } pk;
    if (r < L && r < 49) {
        const float* src = im + ((size_t)i * 50 + r + 1) * DDIM + d0;
        float4 f0 = ((const float4*)src)[0];
        float4 f1 = ((const float4*)src)[1];
        pk.h[0] = __float22half2_rn(make_float2(f0.x, f0.y));
        pk.h[1] = __float22half2_rn(make_float2(f0.z, f0.w));
        pk.h[2] = __float22half2_rn(make_float2(f1.x, f1.y));
        pk.h[3] = __float22half2_rn(make_float2(f1.z, f1.w));
    } else {
        pk.v = make_uint4(0, 0, 0, 0);
    }
    *((uint4*)(g_A + ((size_t)i * AROWS + r) * DDIM + d0)) = pk.v;
}

__global__ void convS_kernel(const float* __restrict__ s, const int* __restrict__ s_len) {
    int u = blockIdx.x * blockDim.x + threadIdx.x;        // < 128*40*128
    int i   = u / (SROWS * 128);
    int rem = u - i * (SROWS * 128);
    int r  = rem >> 7;
    int d0 = (rem & 127) << 3;
    int L = s_len[i] - 3;
    union { uint4 v; __half2 h[4]; } pk;
    if (r < L && r < 37) {
        const float* src = s + ((size_t)i * 40 + r + 1) * DDIM + d0;
        float4 f0 = ((const float4*)src)[0];
        float4 f1 = ((const float4*)src)[1];
        pk.h[0] = __float22half2_rn(make_float2(f0.x, f0.y));
        pk.h[1] = __float22half2_rn(make_float2(f0.z, f0.w));
        pk.h[2] = __float22half2_rn(make_float2(f1.x, f1.y));
        pk.h[3] = __float22half2_rn(make_float2(f1.z, f1.w));
    } else {
        pk.v = make_uint4(0, 0, 0, 0);
    }
    *((uint4*)(g_S + ((size_t)i * SROWS + r) * DDIM + d0)) = pk.v;
}

// ------------- GEMM + fused masked max/sum epilogue -------------
// CTA: 512 threads, tile M=128 (2 i), N=320 (8 j x 40), K=1024 in 16 chunks of 64.
// Warp grid 4(m) x 4(n): warp tile 32 x 80.
// SMEM stage: A 128x144 + B 320x144 = 64512 B; 3 stages = 193536 B (1 CTA/SM).
#define PITCH     144
#define ASTAGE    18432              // 128*144
#define STAGE_SZ  64512              // ASTAGE + 320*144
#define SMEM_BYTES (STAGE_SZ * 3)
#define CPITCH    326                // C pitch in floats: EVEN (float2-aligned);
                                     // 326*4 % 128 = 24 -> fragment rows hit distinct banks

__device__ __forceinline__ void load_stage(uint32_t sbase, int stg, int kt,
                                           int ib, int jb, int tid) {
    uint32_t sa = sbase + stg * STAGE_SZ;
    const __half* gA = g_A + ((size_t)ib * 128) * DDIM + kt * 64;
    const __half* gB = g_S + ((size_t)jb * 320) * DDIM + kt * 64;
#pragma unroll
    for (int q = 0; q < 2; q++) {                         // A: 1024 16B chunks
        int idx = tid + q * 512;
        int row = idx >> 3, c = idx & 7;
        CP_ASYNC16(sa + row * PITCH + c * 16,
                   (const char*)(gA + (size_t)row * DDIM) + c * 16);
    }
#pragma unroll
    for (int q = 0; q < 5; q++) {                         // B: 2560 16B chunks
        int idx = tid + q * 512;
        int row = idx >> 3, c = idx & 7;
        CP_ASYNC16(sa + ASTAGE + row * PITCH + c * 16,
                   (const char*)(gB + (size_t)row * DDIM) + c * 16);
    }
}

__global__ void __launch_bounds__(512, 1) align_gemm_kernel(float* __restrict__ out) {
    extern __shared__ __align__(16) char smem[];
    const int tid  = threadIdx.x;
    const int lane = tid & 31;
    const int wid  = tid >> 5;
    const int wm   = wid & 3;        // M offset wm*32
    const int wn   = wid >> 2;       // N offset wn*80
    const int jb = blockIdx.x;       // 0..15
    const int ib = blockIdx.y;       // 0..63
    const uint32_t sbase = smem_u32(smem);

    const int quad = lane >> 3, r8 = lane & 7;
    const uint32_t a_lane = (uint32_t)((wm * 32 + (quad & 1) * 8 + r8) * PITCH + (quad >> 1) * 16);
    uint32_t b_lane[5];
#pragma unroll
    for (int nn = 0; nn < 5; nn++)
        b_lane[nn] = (uint32_t)(ASTAGE + (wn * 80 + nn * 16 + (quad >> 1) * 8 + r8) * PITCH
                                + (quad & 1) * 16);

    float c[2][10][4];
#pragma unroll
    for (int mt = 0; mt < 2; mt++)
#pragma unroll
        for (int nt = 0; nt < 10; nt++)
#pragma unroll
            for (int q = 0; q < 4; q++) c[mt][nt][q] = 0.0f;

    load_stage(sbase, 0, 0, ib, jb, tid); CP_COMMIT();
    load_stage(sbase, 1, 1, ib, jb, tid); CP_COMMIT();
    load_stage(sbase, 2, 2, ib, jb, tid); CP_COMMIT();

    int stg = 0;
#pragma unroll 1
    for (int kt = 0; kt < 16; kt++) {
        CP_WAIT2();
        __syncthreads();

        const uint32_t stga = sbase + stg * STAGE_SZ;
#pragma unroll
        for (int step = 0; step < 4; step++) {
            uint32_t areg[2][4], breg[5][4];
#pragma unroll
            for (int mt = 0; mt < 2; mt++)
                LDSM4(areg[mt], stga + a_lane + mt * 16 * PITCH + step * 32);
#pragma unroll
            for (int nn = 0; nn < 5; nn++)
                LDSM4(breg[nn], stga + b_lane[nn] + step * 32);
#pragma unroll
            for (int mt = 0; mt < 2; mt++)
#pragma unroll
                for (int nt = 0; nt < 10; nt++)
                    MMA16816(c[mt][nt], areg[mt], breg[nt >> 1][(nt & 1) * 2],
                             breg[nt >> 1][(nt & 1) * 2 + 1]);
        }
        __syncthreads();   // all warps done reading stage stg before overwrite
        if (kt + 3 < 16) load_stage(sbase, stg, kt + 3, ib, jb, tid);
        CP_COMMIT();       // empty commits at tail keep wait_group semantics
        stg = (stg + 1 == 3) ? 0 : stg + 1;
    }
    __syncthreads();       // compute done; smem reused for C

    // ---- store C tile to smem: [128][CPITCH] floats ----
    float* C   = (float*)smem;
    float* acc = (float*)(smem + 128 * CPITCH * 4);   // 16 floats (2 i x 8 j)
    float* red = acc + 16;                            // 2*320 floats
    if (tid < 16) acc[tid] = 0.0f;
#pragma unroll
    for (int mt = 0; mt < 2; mt++)
#pragma unroll
        for (int nt = 0; nt < 10; nt++) {
            int row = wm * 32 + mt * 16 + (lane >> 2);
            int col = wn * 80 + nt * 8 + (lane & 3) * 2;
            *(float2*)&C[row * CPITCH + col]       = make_float2(c[mt][nt][0], c[mt][nt][1]);
            *(float2*)&C[(row + 8) * CPITCH + col] = make_float2(c[mt][nt][2], c[mt][nt][3]);
        }
    __syncthreads();

    // ---- row part: row r (<49 per il), max over w<37 per j-block, summed over r ----
    {
        int row = tid & 127;
        int jpair = tid >> 7;              // 2 j-blocks per thread
        int il = row >> 6, ro = row & 63;
        const float* Cr = &C[row * CPITCH];
#pragma unroll
        for (int jj = 0; jj < 2; jj++) {
            int jblock = jpair * 2 + jj;
            float rm = Cr[jblock * 40];
#pragma unroll
            for (int w = 1; w < 37; w++) rm = fmaxf(rm, Cr[jblock * 40 + w]);
            float rs = wsum((ro < 49) ? rm : 0.0f);
            if (lane == 0) atomicAdd(&acc[il * 8 + jblock], rs);
        }
    }
    // ---- col part: col w (<37 per j-block), max over r<49 ----
    if (tid < 320) {
        int w = tid % 40;
#pragma unroll
        for (int il = 0; il < 2; il++) {
            const float* Cc = &C[il * 64 * CPITCH + tid];
            float cm = Cc[0];
#pragma unroll
            for (int r = 1; r < 49; r++) cm = fmaxf(cm, Cc[r * CPITCH]);
            red[il * 320 + tid] = (w < 37) ? cm : 0.0f;
        }
    }
    __syncthreads();
    if (tid < 16) {
        int il = tid >> 3, jj = tid & 7;
        float sum = acc[tid];
        const float* rp = &red[il * 320 + jj * 40];
#pragma unroll
        for (int w = 0; w < 37; w++) sum += rp[w];
        out[(ib * 2 + il) * NBATCH + jb * 8 + jj] = sum;
    }
}

extern "C" void kernel_launch(void* const* d_in, const int* in_sizes, int n_in,
                              void* d_out, int out_size) {
    (void)in_sizes; (void)n_in; (void)out_size;
    const float* im   = (const float*)d_in[0];
    const float* s    = (const float*)d_in[1];
    const int* im_len = (const int*)d_in[2];
    const int* s_len  = (const int*)d_in[3];
    float* out = (float*)d_out;

    convA_kernel<<<4096, 256>>>(im, im_len);
    convS_kernel<<<2560, 256>>>(s, s_len);

    cudaFuncSetAttribute(align_gemm_kernel,
                         cudaFuncAttributeMaxDynamicSharedMemorySize, SMEM_BYTES);
    dim3 grid(16, 64);
    align_gemm_kernel<<<grid, 512, SMEM_BYTES>>>(out);
}